// round 14
// baseline (speedup 1.0000x reference)
#include <cuda_runtime.h>
#include <math.h>

#define Hdim 512
#define G4   2048
#define NB   256      // B*U lstm lanes
#define LT   64       // timesteps
#define BB   8
#define UU   32
#define SS   2048
#define EE   128
#define NNODE 33      // U+1
#define LSTM_GRID 128

typedef unsigned long long u64;

__device__ __forceinline__ u64 pk2(float lo, float hi){
  u64 r; asm("mov.b64 %0, {%1,%2};" : "=l"(r) : "r"(__float_as_uint(lo)), "r"(__float_as_uint(hi))); return r;
}
__device__ __forceinline__ u64 fma2(u64 a, u64 b, u64 c){
  u64 d; asm("fma.rn.f32x2 %0, %1, %2, %3;" : "=l"(d) : "l"(a), "l"(b), "l"(c)); return d;
}
__device__ __forceinline__ u64 add2(u64 a, u64 b){
  u64 d; asm("add.rn.f32x2 %0, %1, %2;" : "=l"(d) : "l"(a), "l"(b)); return d;
}
__device__ __forceinline__ void upk2(u64 v, float& lo, float& hi){
  unsigned l_, h_; asm("mov.b64 {%0,%1}, %2;" : "=r"(l_), "=r"(h_) : "l"(v));
  lo = __uint_as_float(l_); hi = __uint_as_float(h_);
}

// ---------------- scratch (device globals; no allocations allowed) ----------
__device__ float g_x  [(size_t)LT*NB*Hdim];
__device__ float g_gx [(size_t)LT*NB*G4];
__device__ float g_ys [(size_t)LT*NB*Hdim];
__device__ float g_h  [2][NB*Hdim];
__device__ float g_nodes[BB*NNODE*Hdim];
__device__ float g_msg  [(size_t)BB*EE*Hdim];
__device__ float g_agg  [BB*NNODE*Hdim];
__device__ float g_new  [BB*NNODE*Hdim];
__device__ unsigned g_bar4[4];

// ---------------- output offsets (pytree flatten order) ---------------------
#define OFF_ENCH 0
#define OFF_ENCC 4096
#define OFF_MB   8192
#define OFF_LEN1 (8192 + 8388608)
#define OFF_MBU  (OFF_LEN1 + 8)
#define OFF_LEN2 (OFF_MBU + 8388608)
#define OFF_HIER (OFF_LEN2 + 8)

__device__ __forceinline__ float sigmf(float x){ return 1.0f/(1.0f+expf(-x)); }
__device__ __forceinline__ float sigmf_fast(float x){ return 1.0f/(1.0f+__expf(-x)); }
__device__ __forceinline__ float tanh_fast(float x){ return 2.0f/(1.0f+__expf(-2.0f*x)) - 1.0f; }

// ---------------- init: zero h0, barriers ------------------------------------
__global__ void k_zero(){
  int i = blockIdx.x*blockDim.x + threadIdx.x;
  if (i < NB*Hdim){ g_h[0][i] = 0.0f; }
  if (i < 4) g_bar4[i] = 0u;
}

// ---------------- embedding gather -----------------------------------------
__global__ void k_embed(const int* __restrict__ src, const int* __restrict__ speaker,
                        const float* __restrict__ emb, const float* __restrict__ spkt){
  int row = blockIdx.x;            // t*256 + n
  int t = row >> 8, n = row & 255;
  int b = n >> 5, u = n & 31;
  int s = u*LT + t;
  int w  = src[s*BB + b];
  int sp = speaker[b*SS + s];
  const float* er = emb  + (size_t)w  * Hdim;
  const float* sr = spkt + (size_t)sp * Hdim;
  float* xr = g_x + (size_t)row * Hdim;
  for (int h = threadIdx.x; h < Hdim; h += blockDim.x)
    xr[h] = er[h] + sr[h];
}

// ---------------- Gx = x @ W_ih + b ; M=16384 N=2048 K=512 ------------------
#define GX_PAD 130
__global__ void __launch_bounds__(256) k_gx_gemm(const float* __restrict__ Wih,
                                                 const float* __restrict__ bias){
  __shared__ float As[2][16][GX_PAD];
  __shared__ float Bs[2][16][64];
  int tid = threadIdx.x;
  int m0 = blockIdx.y*128, n0 = blockIdx.x*64;
  int tr = tid>>4, tc = tid&15;
  int s_arow = tid>>2, s_ak = (tid&3)<<2;
  int s_bk = tid>>4, s_bn = (tid&15)<<2;

  const float* Ap = g_x + (size_t)(m0 + s_arow)*Hdim + s_ak;
  const float* Bp = Wih + (size_t)s_bk*G4 + n0 + s_bn;

  float4 ra0 = *(const float4*)Ap;
  float4 ra1 = *(const float4*)(Ap + (size_t)64*Hdim);
  float4 rb  = *(const float4*)Bp;

  u64 acc[4][4];
  #pragma unroll
  for (int r=0;r<4;r++){ acc[r][0]=0; acc[r][1]=0; acc[r][2]=0; acc[r][3]=0; }

  int buf = 0;
  for (int k0 = 0; k0 < Hdim; k0 += 16){
    As[buf][s_ak+0][s_arow]    = ra0.x; As[buf][s_ak+1][s_arow]    = ra0.y;
    As[buf][s_ak+2][s_arow]    = ra0.z; As[buf][s_ak+3][s_arow]    = ra0.w;
    As[buf][s_ak+0][s_arow+64] = ra1.x; As[buf][s_ak+1][s_arow+64] = ra1.y;
    As[buf][s_ak+2][s_arow+64] = ra1.z; As[buf][s_ak+3][s_arow+64] = ra1.w;
    *(float4*)&Bs[buf][s_bk][s_bn] = rb;
    __syncthreads();
    if (k0 + 16 < Hdim){
      Ap += 16; Bp += (size_t)16*G4;
      ra0 = *(const float4*)Ap;
      ra1 = *(const float4*)(Ap + (size_t)64*Hdim);
      rb  = *(const float4*)Bp;
    }
    #pragma unroll
    for (int kk = 0; kk < 16; kk++){
      const float* Ak = &As[buf][kk][tr<<3];
      u64 a0 = *(const u64*)(Ak);
      u64 a1 = *(const u64*)(Ak+2);
      u64 a2 = *(const u64*)(Ak+4);
      u64 a3 = *(const u64*)(Ak+6);
      float4 b = *(const float4*)&Bs[buf][kk][tc<<2];
      u64 b0 = pk2(b.x,b.x), b1 = pk2(b.y,b.y), b2 = pk2(b.z,b.z), b3 = pk2(b.w,b.w);
      acc[0][0]=fma2(a0,b0,acc[0][0]); acc[0][1]=fma2(a0,b1,acc[0][1]);
      acc[0][2]=fma2(a0,b2,acc[0][2]); acc[0][3]=fma2(a0,b3,acc[0][3]);
      acc[1][0]=fma2(a1,b0,acc[1][0]); acc[1][1]=fma2(a1,b1,acc[1][1]);
      acc[1][2]=fma2(a1,b2,acc[1][2]); acc[1][3]=fma2(a1,b3,acc[1][3]);
      acc[2][0]=fma2(a2,b0,acc[2][0]); acc[2][1]=fma2(a2,b1,acc[2][1]);
      acc[2][2]=fma2(a2,b2,acc[2][2]); acc[2][3]=fma2(a2,b3,acc[2][3]);
      acc[3][0]=fma2(a3,b0,acc[3][0]); acc[3][1]=fma2(a3,b1,acc[3][1]);
      acc[3][2]=fma2(a3,b2,acc[3][2]); acc[3][3]=fma2(a3,b3,acc[3][3]);
    }
    buf ^= 1;
  }
  int mrow = m0 + (tr<<3);
  int ncol = n0 + (tc<<2);
  float b0 = bias[ncol], b1 = bias[ncol+1], b2 = bias[ncol+2], b3 = bias[ncol+3];
  #pragma unroll
  for (int rp = 0; rp < 4; rp++){
    float r0c0,r1c0,r0c1,r1c1,r0c2,r1c2,r0c3,r1c3;
    upk2(acc[rp][0], r0c0, r1c0);
    upk2(acc[rp][1], r0c1, r1c1);
    upk2(acc[rp][2], r0c2, r1c2);
    upk2(acc[rp][3], r0c3, r1c3);
    *(float4*)&g_gx[(size_t)(mrow + rp*2    )*G4 + ncol] = make_float4(r0c0+b0, r0c1+b1, r0c2+b2, r0c3+b3);
    *(float4*)&g_gx[(size_t)(mrow + rp*2 + 1)*G4 + ncol] = make_float4(r1c0+b0, r1c1+b1, r1c2+b2, r1c3+b3);
  }
}

// ---------------- persistent LSTM v3: 256 thr, 4-way split-K, 8r x 2h tile --
// grid 128 CTAs = 4 mt x 32 hs. thread: ks=tid>>6 (k-quarter), th=tid&63:
//   rg=th>>3 (8 rows each), jp=th&7 (hidden pair). acc = 8 rows x 2 hid x 4 g.
#define AS_PAD 68
#define WS_FLOATS (512*64)
#define A_FLOATS  (2*4*32*AS_PAD)
#define SMEM_LSTM ((WS_FLOATS + A_FLOATS) * 4)

extern __shared__ float smem_dyn[];

__global__ void __launch_bounds__(256, 1) k_lstm_persist(const float* __restrict__ Whh){
  float* Ws = smem_dyn;                 // [k][jp*8 + g*2 + u]
  float* As = smem_dyn + WS_FLOATS;     // [buf][ks][kk][AS_PAD], [k][row] transposed
  int tid = threadIdx.x;
  int hs = blockIdx.x & 31;
  int mt = blockIdx.x >> 5;
  int m0 = mt << 6;

  // pack Whh slice: Ws[k][jp*8+g*2+u] = Whh[k][g*512 + hs*16 + jp*2 + u]
  {
    int col = tid & 63;
    int jp_ = col >> 3, g_ = (col >> 1) & 3, u_ = col & 1;
    int wcol = g_*512 + hs*16 + jp_*2 + u_;
    for (int k = (tid>>6); k < 512; k += 4)
      Ws[k*64 + col] = Whh[(size_t)k*G4 + wcol];
  }
  __syncthreads();

  int ks = tid >> 6;            // k-quarter 0..3
  int th = tid & 63;
  int rg = th >> 3;             // rowgroup (8 rows)
  int jp = th & 7;              // hidden pair
  int ksbase = ks << 7;

  // epilogue cell ownership: thread e handles cell-pairs p = 2e, 2e+1
  int prow[2], phid[2];
  #pragma unroll
  for (int j = 0; j < 2; j++){
    int p = 2*tid + j;
    int u_ = p >> 8, rp_ = (p >> 6) & 3, t2 = p & 63;
    prow[j] = m0 + (t2>>3)*8 + rp_*2;          // rows prow[j], prow[j]+1
    phid[j] = hs*16 + (t2&7)*2 + u_;
  }
  float cc[2][2] = {{0.f,0.f},{0.f,0.f}};

  // gx prefetch for step 0
  float pgx[2][2][4];
  #pragma unroll
  for (int j = 0; j < 2; j++)
    #pragma unroll
    for (int rr = 0; rr < 2; rr++){
      const float* gb = g_gx + (size_t)(prow[j]+rr)*G4 + phid[j];
      pgx[j][rr][0] = __ldcg(gb);
      pgx[j][rr][1] = __ldcg(gb + 512);
      pgx[j][rr][2] = __ldcg(gb + 1024);
      pgx[j][rr][3] = __ldcg(gb + 1536);
    }

  #pragma unroll 1
  for (int t = 0; t < LT; t++){
    const float* hprev = g_h[t & 1];
    float*       hnext = g_h[(t+1) & 1];

    u64 acc[32];                       // [(g*2+u)*4 + rp]
    #pragma unroll
    for (int i=0;i<32;i++) acc[i] = 0ull;

    // staging: thread stages row m0+th, its quarter's k-range, chunks of 32
    const float* hrow = hprev + (size_t)(m0+th)*Hdim + ksbase;
    float4 pf[8];
    #pragma unroll
    for (int i=0;i<8;i++) pf[i] = __ldcg((const float4*)(hrow + i*4));

    int buf = 0;
    #pragma unroll 1
    for (int c = 0; c < 4; c++){
      float* A = As + (size_t)((buf<<2) + ks)*32*AS_PAD;
      #pragma unroll
      for (int i=0;i<8;i++){
        A[(i*4+0)*AS_PAD + th] = pf[i].x;
        A[(i*4+1)*AS_PAD + th] = pf[i].y;
        A[(i*4+2)*AS_PAD + th] = pf[i].z;
        A[(i*4+3)*AS_PAD + th] = pf[i].w;
      }
      __syncthreads();
      if (c < 3){
        #pragma unroll
        for (int i=0;i<8;i++) pf[i] = __ldcg((const float4*)(hrow + (c+1)*32 + i*4));
      }
      const float* Wbase = Ws + (size_t)(ksbase + c*32)*64 + (jp<<3);
      const float* Ab = A + (rg<<3);
      #pragma unroll 8
      for (int kk = 0; kk < 32; kk++){
        ulonglong2 av0 = *(const ulonglong2*)(Ab + kk*AS_PAD);
        ulonglong2 av1 = *(const ulonglong2*)(Ab + kk*AS_PAD + 4);
        u64 a0 = av0.x, a1 = av0.y, a2 = av1.x, a3 = av1.y;
        float4 w0 = *(const float4*)(Wbase + kk*64);
        float4 w1 = *(const float4*)(Wbase + kk*64 + 4);
        u64 b00 = pk2(w0.x,w0.x), b01 = pk2(w0.y,w0.y);
        u64 b10 = pk2(w0.z,w0.z), b11 = pk2(w0.w,w0.w);
        u64 b20 = pk2(w1.x,w1.x), b21 = pk2(w1.y,w1.y);
        u64 b30 = pk2(w1.z,w1.z), b31 = pk2(w1.w,w1.w);
        acc[ 0]=fma2(a0,b00,acc[ 0]); acc[ 1]=fma2(a1,b00,acc[ 1]); acc[ 2]=fma2(a2,b00,acc[ 2]); acc[ 3]=fma2(a3,b00,acc[ 3]);
        acc[ 4]=fma2(a0,b01,acc[ 4]); acc[ 5]=fma2(a1,b01,acc[ 5]); acc[ 6]=fma2(a2,b01,acc[ 6]); acc[ 7]=fma2(a3,b01,acc[ 7]);
        acc[ 8]=fma2(a0,b10,acc[ 8]); acc[ 9]=fma2(a1,b10,acc[ 9]); acc[10]=fma2(a2,b10,acc[10]); acc[11]=fma2(a3,b10,acc[11]);
        acc[12]=fma2(a0,b11,acc[12]); acc[13]=fma2(a1,b11,acc[13]); acc[14]=fma2(a2,b11,acc[14]); acc[15]=fma2(a3,b11,acc[15]);
        acc[16]=fma2(a0,b20,acc[16]); acc[17]=fma2(a1,b20,acc[17]); acc[18]=fma2(a2,b20,acc[18]); acc[19]=fma2(a3,b20,acc[19]);
        acc[20]=fma2(a0,b21,acc[20]); acc[21]=fma2(a1,b21,acc[21]); acc[22]=fma2(a2,b21,acc[22]); acc[23]=fma2(a3,b21,acc[23]);
        acc[24]=fma2(a0,b30,acc[24]); acc[25]=fma2(a1,b30,acc[25]); acc[26]=fma2(a2,b30,acc[26]); acc[27]=fma2(a3,b30,acc[27]);
        acc[28]=fma2(a0,b31,acc[28]); acc[29]=fma2(a1,b31,acc[29]); acc[30]=fma2(a2,b31,acc[30]); acc[31]=fma2(a3,b31,acc[31]);
      }
      buf ^= 1;
    }

    // --- split-K reduction: all slices dump partials, all threads reduce ----
    __syncthreads();
    u64* red = (u64*)As;               // 4*2048 u64 = 64 KB overlay
    {
      u64* rbase = red + (size_t)ks*2048;
      #pragma unroll
      for (int g = 0; g < 4; g++)
        #pragma unroll
        for (int u_ = 0; u_ < 2; u_++)
          #pragma unroll
          for (int rp_ = 0; rp_ < 4; rp_++)
            rbase[g*512 + u_*256 + rp_*64 + th] = acc[(g*2+u_)*4 + rp_];
    }
    __syncthreads();

    // thread e reduces its 2 cell-pairs x 4 gates across the 4 slices
    u64 gv[4][2];
    #pragma unroll
    for (int g = 0; g < 4; g++){
      ulonglong2 s0 = *(const ulonglong2*)(red +        g*512 + 2*tid);
      ulonglong2 s1 = *(const ulonglong2*)(red + 2048 + g*512 + 2*tid);
      ulonglong2 s2 = *(const ulonglong2*)(red + 4096 + g*512 + 2*tid);
      ulonglong2 s3 = *(const ulonglong2*)(red + 6144 + g*512 + 2*tid);
      gv[g][0] = add2(add2(s0.x, s1.x), add2(s2.x, s3.x));
      gv[g][1] = add2(add2(s0.y, s1.y), add2(s2.y, s3.y));
    }

    // epilogue: 4 cells per thread
    float* ys = g_ys + (size_t)t*NB*Hdim;
    #pragma unroll
    for (int j = 0; j < 2; j++){
      float ii[2], ff[2], gg[2], oo[2];
      upk2(gv[0][j], ii[0], ii[1]);
      upk2(gv[1][j], ff[0], ff[1]);
      upk2(gv[2][j], gg[0], gg[1]);
      upk2(gv[3][j], oo[0], oo[1]);
      #pragma unroll
      for (int rr = 0; rr < 2; rr++){
        float i_ = ii[rr] + pgx[j][rr][0];
        float f_ = ff[rr] + pgx[j][rr][1];
        float g_ = gg[rr] + pgx[j][rr][2];
        float o_ = oo[rr] + pgx[j][rr][3];
        float c_ = sigmf_fast(f_)*cc[j][rr] + sigmf_fast(i_)*tanh_fast(g_);
        float h_ = sigmf_fast(o_)*tanh_fast(c_);
        cc[j][rr] = c_;
        int n = prow[j] + rr;
        hnext[(size_t)n*Hdim + phid[j]] = h_;
        ys   [(size_t)n*Hdim + phid[j]] = h_;
      }
    }

    // gx prefetch for next step (hides under the barrier wait)
    if (t < LT-1){
      const float* gx = g_gx + (size_t)(t+1)*NB*G4;
      #pragma unroll
      for (int j = 0; j < 2; j++)
        #pragma unroll
        for (int rr = 0; rr < 2; rr++){
          const float* gb = gx + (size_t)(prow[j]+rr)*G4 + phid[j];
          pgx[j][rr][0] = __ldcg(gb);
          pgx[j][rr][1] = __ldcg(gb + 512);
          pgx[j][rr][2] = __ldcg(gb + 1024);
          pgx[j][rr][3] = __ldcg(gb + 1536);
        }
      __threadfence();
      __syncthreads();
      if (tid == 0){
        atomicAdd(&g_bar4[mt], 1u);
        unsigned target = (unsigned)(t+1) * 32u;
        volatile unsigned* vb = &g_bar4[mt];
        while (*vb < target) { }
      }
      __syncthreads();
    }
  }
}

// ---------------- GNN: build nodes ------------------------------------------
__global__ void k_nodes(){
  int b = blockIdx.x, h = threadIdx.x;
  const float* last = g_ys + (size_t)(LT-1)*NB*Hdim;
  float s = 0.0f;
  for (int u = 0; u < UU; u++){
    float v = last[(size_t)(b*UU + u)*Hdim + h];
    g_nodes[(size_t)(b*NNODE + u)*Hdim + h] = v;
    s += v;
  }
  g_nodes[(size_t)(b*NNODE + UU)*Hdim + h] = s * (1.0f/UU);
}

// ---------------- per-edge message ------------------------------------------
__global__ void __launch_bounds__(256) k_msg(const int* __restrict__ edge_src,
                                             const int* __restrict__ rels,
                                             const float* __restrict__ Wrel){
  int be = blockIdx.x;
  int b = be >> 7;
  int rel = rels[be];
  int es  = edge_src[be];
  __shared__ float xs[Hdim];
  int tid = threadIdx.x;
  xs[tid]     = g_nodes[(size_t)(b*NNODE + es)*Hdim + tid];
  xs[tid+256] = g_nodes[(size_t)(b*NNODE + es)*Hdim + tid + 256];
  __syncthreads();
  const float* W = Wrel + (size_t)rel*Hdim*Hdim;
  float a0 = 0.0f, a1 = 0.0f;
  for (int k = 0; k < Hdim; k++){
    float xv = xs[k];
    a0 += xv * W[(size_t)k*Hdim + tid];
    a1 += xv * W[(size_t)k*Hdim + tid + 256];
  }
  g_msg[(size_t)be*Hdim + tid]       = a0;
  g_msg[(size_t)be*Hdim + tid + 256] = a1;
}

// ---------------- deterministic segment-sum ---------------------------------
__global__ void k_agg(const int* __restrict__ edge_dst){
  int bd = blockIdx.x;
  int b = bd / NNODE, d = bd % NNODE;
  int h = threadIdx.x;
  float a = 0.0f;
  for (int e = 0; e < EE; e++){
    if (edge_dst[b*EE + e] == d)
      a += g_msg[(size_t)(b*EE + e)*Hdim + h];
  }
  g_agg[(size_t)bd*Hdim + h] = a;
}

// ---------------- GNN output/gate fusion ------------------------------------
__global__ void __launch_bounds__(256) k_gnn(const float* __restrict__ Wself,
                                             const float* __restrict__ bg,
                                             const float* __restrict__ Wg1,
                                             const float* __restrict__ Wg2){
  int bd = blockIdx.x;
  __shared__ float nd[Hdim], ag[Hdim];
  int tid = threadIdx.x;
  nd[tid]     = g_nodes[(size_t)bd*Hdim + tid];
  nd[tid+256] = g_nodes[(size_t)bd*Hdim + tid + 256];
  ag[tid]     = g_agg[(size_t)bd*Hdim + tid];
  ag[tid+256] = g_agg[(size_t)bd*Hdim + tid + 256];
  __syncthreads();
  for (int jo = 0; jo < 2; jo++){
    int j = tid + jo*256;
    float s1 = 0.0f, s2 = 0.0f, s3 = 0.0f;
    for (int k = 0; k < Hdim; k++){
      float nv = nd[k], av = ag[k];
      s1 += nv * Wself[(size_t)k*Hdim + j];
      s2 += nv * Wg1  [(size_t)k*Hdim + j];
      s3 += av * Wg2  [(size_t)k*Hdim + j];
    }
    float outv = s1 + ag[j] + bg[j];
    outv = outv > 0.0f ? outv : 0.0f;
    float gate = sigmf(s2 + s3);
    g_new[(size_t)bd*Hdim + j] = gate*outv + (1.0f - gate)*nd[j];
  }
}

// ---------------- output writers --------------------------------------------
__global__ void k_out_small(float* __restrict__ dout, const int* __restrict__ lengths){
  int i = blockIdx.x*blockDim.x + threadIdx.x;
  if (i < 4096){
    int b = i >> 9, h = i & 511;
    float v = g_new[(size_t)(b*NNODE + UU)*Hdim + h];
    dout[OFF_ENCH + i] = v;
    dout[OFF_ENCC + i] = v;
  }
  if (i < 8){
    float lv = (float)lengths[i];
    dout[OFF_LEN1 + i] = lv;
    dout[OFF_LEN2 + i] = lv;
  }
  dout[OFF_HIER + i] = (float)LT;
}

__global__ void k_big_out(float* __restrict__ dout){
  size_t i = (size_t)blockIdx.x*blockDim.x + threadIdx.x;
  if (i >= (size_t)SS*BB*Hdim) return;
  int h = (int)(i & 511);
  int b = (int)((i >> 9) & 7);
  int s = (int)(i >> 12);
  int t = s & 63, u = s >> 6;
  dout[OFF_MB  + i] = g_ys[((size_t)t*NB + b*UU + u)*Hdim + h];
  dout[OFF_MBU + i] = g_new[(size_t)(b*NNODE + u)*Hdim + h];
}

// ---------------- driver -----------------------------------------------------
extern "C" void kernel_launch(void* const* d_in, const int* in_sizes, int n_in,
                              void* d_out, int out_size){
  const int*   src      = (const int*)  d_in[0];
  const int*   speaker  = (const int*)  d_in[2];
  const int*   lengths  = (const int*)  d_in[3];
  const int*   edge_src = (const int*)  d_in[4];
  const int*   edge_dst = (const int*)  d_in[5];
  const int*   rels     = (const int*)  d_in[6];
  const float* emb      = (const float*)d_in[7];
  const float* spkt     = (const float*)d_in[8];
  const float* Wih      = (const float*)d_in[9];
  const float* Whh      = (const float*)d_in[10];
  const float* bl       = (const float*)d_in[11];
  const float* Wrel     = (const float*)d_in[12];
  const float* Wself    = (const float*)d_in[13];
  const float* bg       = (const float*)d_in[14];
  const float* Wg1      = (const float*)d_in[15];
  const float* Wg2      = (const float*)d_in[16];
  float* dout = (float*)d_out;

  cudaFuncSetAttribute(k_lstm_persist, cudaFuncAttributeMaxDynamicSharedMemorySize, SMEM_LSTM);

  k_zero<<<512, 256>>>();
  k_embed<<<LT*NB, 256>>>(src, speaker, emb, spkt);
  k_gx_gemm<<<dim3(G4/64, (LT*NB)/128), 256>>>(Wih, bl);
  k_lstm_persist<<<LSTM_GRID, 256, SMEM_LSTM>>>(Whh);
  k_nodes<<<BB, 512>>>();
  k_msg<<<BB*EE, 256>>>(edge_src, rels, Wrel);
  k_agg<<<BB*NNODE, 512>>>(edge_dst);
  k_gnn<<<BB*NNODE, 256>>>(Wself, bg, Wg1, Wg2);
  k_out_small<<<64, 256>>>(dout, lengths);
  k_big_out<<<32768, 256>>>(dout);
}